// round 6
// baseline (speedup 1.0000x reference)
#include <cuda_runtime.h>
#include <math.h>

// B=256, T=512, C=512, L=64
#define BN 256
#define TN 512
#define CN 512
#define LN 64
#define SN 129              // 2L+1
#define BLANK 511
#define EPSV 1e-7f
#define RS 8                // row-ring slots
#define KS 5                // states per lane
#define LN2F 0.6931471805599453f
#define FULL 0xffffffffu

// CTC forward DP: one warp per batch element, alpha in registers (5/lane),
// neighbors via shfl. Rows streamed through an 8-slot cp.async ring.
// Software-pipelined: the smem gather for step t+1 is issued at the bottom
// of step t, hiding LDS latency + bank conflicts behind the FP chain.
__global__ __launch_bounds__(32, 8)
void ctc_warp2_kernel(const int* __restrict__ labels,     // [B, L]
                      const float* __restrict__ y_pred,   // [B, T, C]
                      const int* __restrict__ in_len,     // [B, 1]
                      const int* __restrict__ lab_len,    // [B, 1]
                      float* __restrict__ out)            // [B, 1]
{
    const int b    = blockIdx.x;
    const int lane = threadIdx.x;

    __shared__ __align__(16) float rows[RS][CN];   // 16KB ring
    __shared__ float fin[SN];
    __shared__ int   ecap_sh;

    // Extended labels: state s = KS*lane + j
    int  cls[KS];
    bool valid[KS];
    #pragma unroll
    for (int j = 0; j < KS; ++j) {
        int s = KS * lane + j;
        valid[j] = (s < SN);
        int c = BLANK;
        if (valid[j] && (s & 1)) c = labels[b * LN + (s >> 1)];
        cls[j] = valid[j] ? c : 0;
    }
    int cu2 = __shfl_up_sync(FULL, cls[KS - 2], 1);
    int cu1 = __shfl_up_sync(FULL, cls[KS - 1], 1);
    bool alw[KS];
    #pragma unroll
    for (int j = 0; j < KS; ++j) {
        int s   = KS * lane + j;
        int cm2 = (j >= 2) ? cls[j - 2] : ((j == 1) ? cu1 : cu2);
        alw[j] = valid[j] && (s >= 2) && (cls[j] != BLANK) && (cls[j] != cm2);
    }

    const float* base  = y_pred + (size_t)b * TN * CN;
    const int    T_eff = in_len[b];

    // t = 0
    float a[KS];
    #pragma unroll
    for (int j = 0; j < KS; ++j) {
        int s = KS * lane + j;
        a[j] = (s < 2) ? (base[cls[j]] + EPSV) : 0.0f;
    }
    if (T_eff == 1) {
        #pragma unroll
        for (int j = 0; j < KS; ++j)
            if (valid[j]) fin[KS * lane + j] = a[j];
        if (lane == 0) ecap_sh = 0;
    }

    // Prologue: rows 1..7 into ring, one commit group each
    #pragma unroll
    for (int st = 1; st < RS; ++st) {
        #pragma unroll
        for (int k = 0; k < 4; ++k) {
            unsigned dst = (unsigned)__cvta_generic_to_shared(
                &rows[st & (RS - 1)][lane * 4 + k * 128]);
            const float* src = base + (size_t)st * CN + lane * 4 + k * 128;
            asm volatile("cp.async.cg.shared.global [%0], [%1], 16;"
                         :: "r"(dst), "l"(src));
        }
        asm volatile("cp.async.commit_group;");
    }

    // Initial gather: raw probs for step 1 (rows 1,2 complete after wait<=5)
    float praw[KS];
    asm volatile("cp.async.wait_group %0;" :: "n"(RS - 3));
    __syncwarp();
    {
        const float* row = rows[1];
        #pragma unroll
        for (int j = 0; j < KS; ++j) praw[j] = row[cls[j]];
    }

    int   E = 0, pend_e = 0;
    float pend_sc = 1.0f;

    #pragma unroll 8
    for (int t = 1; t < TN; ++t) {
        // Refill slot (t-1)&7 with row t+7
        {
            int st = t + RS - 1;
            if (st < TN) {
                #pragma unroll
                for (int k = 0; k < 4; ++k) {
                    unsigned dst = (unsigned)__cvta_generic_to_shared(
                        &rows[st & (RS - 1)][lane * 4 + k * 128]);
                    const float* src = base + (size_t)st * CN + lane * 4 + k * 128;
                    asm volatile("cp.async.cg.shared.global [%0], [%1], 16;"
                                 :: "r"(dst), "l"(src));
                }
            }
            asm volatile("cp.async.commit_group;");
        }

        float sc512 = 512.0f * pend_sc;
        float epssc = (512.0f * EPSV) * pend_sc;
        E += pend_e; pend_e = 0; pend_sc = 1.0f;

        // pe from prefetched raw probs (identical arithmetic/order as before)
        float pe[KS];
        #pragma unroll
        for (int j = 0; j < KS; ++j)
            pe[j] = valid[j] ? fmaf(praw[j], sc512, epssc) : 0.0f;

        float h1 = __shfl_up_sync(FULL, a[KS - 1], 1);
        float h2 = __shfl_up_sync(FULL, a[KS - 2], 1);
        if (lane == 0) { h1 = 0.0f; h2 = 0.0f; }

        float n0 = (a[0] + h1   + (alw[0] ? h2   : 0.0f)) * pe[0];
        float n1 = (a[1] + a[0] + (alw[1] ? h1   : 0.0f)) * pe[1];
        float n2 = (a[2] + a[1] + (alw[2] ? a[0] : 0.0f)) * pe[2];
        float n3 = (a[3] + a[2] + (alw[3] ? a[1] : 0.0f)) * pe[3];
        float n4 = (a[4] + a[3] + (alw[4] ? a[2] : 0.0f)) * pe[4];
        a[0] = n0; a[1] = n1; a[2] = n2; a[3] = n3; a[4] = n4;

        if ((t & 7) == 0) {
            unsigned u = __float_as_uint(a[0]);
            u = max(u, __float_as_uint(a[1]));
            u = max(u, __float_as_uint(a[2]));
            u = max(u, __float_as_uint(a[3]));
            u = max(u, __float_as_uint(a[4]));
            u = __reduce_max_sync(FULL, u);
            int e = (int)(u >> 23) - 127;
            pend_e  = e;
            pend_sc = __uint_as_float((unsigned)(127 - e) << 23);  // 2^-e
        }

        if (t == T_eff - 1) {
            #pragma unroll
            for (int j = 0; j < KS; ++j)
                if (valid[j]) fin[KS * lane + j] = a[j];
            if (lane == 0) ecap_sh = E;
        }

        // Prefetch gather for step t+1 (row t+1 complete after wait<=RS-3)
        if (t + 1 < TN) {
            asm volatile("cp.async.wait_group %0;" :: "n"(RS - 3));
            __syncwarp();
            const float* row = rows[(t + 1) & (RS - 1)];
            #pragma unroll
            for (int j = 0; j < KS; ++j) praw[j] = row[cls[j]];
        }
    }
    __syncwarp();

    if (lane == 0) {
        int ll = lab_len[b];
        int i1 = 2 * ll;
        int i2 = 2 * ll - 1;
        if (i1 < 0) i1 += SN;
        if (i2 < 0) i2 += SN;
        float x = fin[i1] + fin[i2];
        out[b] = -logf(x) + ((float)(9 * (T_eff - 1) - ecap_sh)) * LN2F;
    }
}

extern "C" void kernel_launch(void* const* d_in, const int* in_sizes, int n_in,
                              void* d_out, int out_size)
{
    const int*   y_true       = (const int*)d_in[0];
    const float* y_pred       = (const float*)d_in[1];
    const int*   input_length = (const int*)d_in[2];
    const int*   label_length = (const int*)d_in[3];
    float*       out          = (float*)d_out;

    ctc_warp2_kernel<<<BN, 32>>>(y_true, y_pred, input_length, label_length, out);
}